// round 6
// baseline (speedup 1.0000x reference)
#include <cuda_runtime.h>
#include <cuda_fp16.h>
#include <math.h>
#include <cstdint>

// Problem constants
#define BB   2
#define KK   8
#define CC   256
#define HW   16384
#define SS   2048
#define SIM_TH 0.95f
#define EPS_DEN 1e-6f
#define EPS_NRM 1e-12f

// Gram tiling
#define TM 128
#define TN 128
#define KC 32                         // f16 channels per stage (smaller => 4 CTAs/SM)
#define NT (SS / TM)                  // 16
#define NPAIR ((NT * (NT + 1)) / 2)   // 136
#define GRID2 (BB * NPAIR)            // 272
#define SROW 40                       // padded smem row (f16): 80B, conflict-free

// Scratch (no allocation allowed)
__device__ __align__(16) __half g_fh[BB][SS][CC];
__device__ float g_m[BB][KK][SS];
__device__ int   g_inv[BB][HW];
__device__ int   g_order[BB][SS];     // (hw<<16) | s, sorted by hw
__device__ float g_num;
__device__ float g_den;
__device__ unsigned g_done;

// cp.async helpers
#define CP_ASYNC16(dst_smem_u32, src_gptr) \
    asm volatile("cp.async.cg.shared.global [%0], [%1], 16;" \
                 :: "r"(dst_smem_u32), "l"(src_gptr))
#define CP_COMMIT() asm volatile("cp.async.commit_group;" ::: "memory")
#define CP_WAIT0()  asm volatile("cp.async.wait_group 0;" ::: "memory")
#define CP_WAIT1()  asm volatile("cp.async.wait_group 1;" ::: "memory")

// ---------------------------------------------------------------------------
// Kernel 0: build hw-sorted sample order per batch (inverse map + compaction)
// grid: BB blocks x 512 threads
// ---------------------------------------------------------------------------
__global__ __launch_bounds__(512)
void prep_kernel(const int* __restrict__ indices)
{
    __shared__ int cnt[512];
    const int b = blockIdx.x;
    const int tid = threadIdx.x;

    if (b == 0 && tid == 0) { g_num = 0.0f; g_den = 0.0f; g_done = 0u; }

    for (int i = tid; i < HW; i += 512) g_inv[b][i] = -1;
    __syncthreads();
    for (int i = tid; i < SS; i += 512) g_inv[b][indices[b * SS + i]] = i;
    __syncthreads();

    const int base = tid * 32;           // 512 * 32 = 16384
    int c = 0;
#pragma unroll 4
    for (int q = 0; q < 32; q++) c += (g_inv[b][base + q] >= 0);
    cnt[tid] = c;
    __syncthreads();

    // Hillis-Steele inclusive scan over 512
    for (int off = 1; off < 512; off <<= 1) {
        int add = (tid >= off) ? cnt[tid - off] : 0;
        __syncthreads();
        cnt[tid] += add;
        __syncthreads();
    }
    int ofs = cnt[tid] - c;              // exclusive prefix
    for (int q = 0; q < 32; q++) {
        int s = g_inv[b][base + q];
        if (s >= 0) g_order[b][ofs++] = ((base + q) << 16) | s;
    }
}

// ---------------------------------------------------------------------------
// Kernel 1: gather in hw-sorted order (DRAM row-buffer friendly).
// One warp per sample; lane covers 8 channels. grid 512 x 256.
// ---------------------------------------------------------------------------
__global__ void gather_kernel(const float* __restrict__ masks,
                              const float* __restrict__ feats)
{
    const int tid  = threadIdx.x;
    const int wid  = tid >> 5;
    const int lane = tid & 31;

    // mask gather (sorted within each k)
    if (tid < 64) {
        int e = blockIdx.x * 64 + tid;          // 32768 = B*K*S
        int b = e / (KK * SS);
        int r = e % (KK * SS);
        int k = r / SS;
        int pos = r % SS;
        int ord = g_order[b][pos];
        int hw = ord >> 16;
        int s  = ord & 0xFFFF;
        float x = masks[(b * KK + k) * HW + hw];
        g_m[b][k][s] = 1.0f / (1.0f + expf(-x));
    }

    const int gwarp = blockIdx.x * 8 + wid;     // 0..4095
    const int b   = gwarp >> 11;
    const int pos = gwarp & 2047;
    const int ord = g_order[b][pos];
    const int hw  = ord >> 16;
    const int s   = ord & 0xFFFF;

    float v[8];
    float ss = 0.0f;
#pragma unroll
    for (int u = 0; u < 8; u++) {
        int c = u * 32 + lane;
        float x = feats[((size_t)(b * CC + c)) * HW + hw];
        v[u] = x;
        ss += x * x;
    }
#pragma unroll
    for (int off = 16; off > 0; off >>= 1)
        ss += __shfl_xor_sync(0xFFFFFFFFu, ss, off);

    float inv = 1.0f / fmaxf(sqrtf(ss), EPS_NRM);
#pragma unroll
    for (int u = 0; u < 8; u++) {
        int c = u * 32 + lane;
        g_fh[b][s][c] = __float2half(v[u] * inv);
    }
}

// ---------------------------------------------------------------------------
// Kernel 2: f16 mma.sync Gram (fp16 acc) + fused affinity + final scalar.
// 256 threads, 8 warps (2x4), warp tile 64x32, KC=32 double-buffered,
// ~49 KB smem => 4 CTAs/SM.
// ---------------------------------------------------------------------------
#define STAGE_ELEMS (TM * SROW)                 // 5120 f16 per matrix per stage
#define SMEM_AB     (2 * 2 * STAGE_ELEMS)       // As+Bs total f16
#define SMEM_BYTES  (SMEM_AB * 2 + (2 * KK * 128 + 16) * 4)

__global__ __launch_bounds__(256, 4)
void gram_affinity_kernel(float* __restrict__ out)
{
    extern __shared__ __align__(16) char dyn[];
    __half* As = (__half*)dyn;                   // [2][128][40]
    __half* Bs = As + 2 * STAGE_ELEMS;           // [2][128][40]
    float* Ms  = (float*)(dyn + SMEM_AB * 2);    // [8][128]
    float* Mt  = Ms + KK * 128;                  // [8][128]
    float* red = Mt + KK * 128;                  // [16]

    const int tid = threadIdx.x;
    const int b = blockIdx.x / NPAIR;
    int p = blockIdx.x % NPAIR;

    int j = 0;
    while (((j + 1) * (j + 2)) / 2 <= p) j++;
    int i = p - (j * (j + 1)) / 2;

    const int s0 = i * TM;
    const int t0 = j * TN;
    const float w = (i == j) ? 1.0f : 2.0f;

    const int lane = tid & 31;
    const int wid  = tid >> 5;
    const int wm   = wid & 1;
    const int wn   = wid >> 1;

    // staging: 512 x 16B per matrix per chunk -> 2 per thread
    const int lrow = tid >> 2;              // rows 0..63 (then +64)
    const int lch  = (tid & 3) * 8;         // f16 col (16B granule)

    const uint32_t as_base = (uint32_t)__cvta_generic_to_shared(As);
    const uint32_t bs_base = (uint32_t)__cvta_generic_to_shared(Bs);

    // stage 0
#pragma unroll
    for (int it = 0; it < 2; it++) {
        int row = lrow + it * 64;
        uint32_t soff = (uint32_t)(row * SROW + lch) * 2;
        CP_ASYNC16(as_base + soff, &g_fh[b][s0 + row][lch]);
        CP_ASYNC16(bs_base + soff, &g_fh[b][t0 + row][lch]);
    }
    CP_COMMIT();

    // m tiles while stage 0 is in flight
#pragma unroll
    for (int it = 0; it < 4; it++) {
        int q = tid + it * 256;
        int k = q >> 7;
        int r = q & 127;
        Ms[k * 128 + r] = g_m[b][k][s0 + r];
        Mt[k * 128 + r] = g_m[b][k][t0 + r];
    }

    uint32_t acc[4][4][2];
#pragma unroll
    for (int im = 0; im < 4; im++)
#pragma unroll
        for (int in = 0; in < 4; in++) { acc[im][in][0] = 0u; acc[im][in][1] = 0u; }

    const int a_r   = lane & 15;
    const int a_sel = (lane >> 4) << 3;
    const int b_r   = (lane & 7) + ((lane >> 4) << 3);
    const int b_sel = ((lane >> 3) & 1) << 3;

#pragma unroll 1
    for (int ck = 0; ck < 8; ck++) {
        if (ck < 7) {
            const int kcn = (ck + 1) * KC;
            const int stn = (ck + 1) & 1;
#pragma unroll
            for (int it = 0; it < 2; it++) {
                int row = lrow + it * 64;
                uint32_t soff = (uint32_t)(stn * STAGE_ELEMS + row * SROW + lch) * 2;
                CP_ASYNC16(as_base + soff, &g_fh[b][s0 + row][kcn + lch]);
                CP_ASYNC16(bs_base + soff, &g_fh[b][t0 + row][kcn + lch]);
            }
            CP_COMMIT();
            CP_WAIT1();
        } else {
            CP_WAIT0();
        }
        __syncthreads();

        const int st = ck & 1;
        __half* Ac = As + st * STAGE_ELEMS;
        __half* Bc = Bs + st * STAGE_ELEMS;

#pragma unroll
        for (int kk = 0; kk < KC; kk += 16) {
            unsigned af[4][4];
#pragma unroll
            for (int im = 0; im < 4; im++) {
                unsigned addr = (unsigned)__cvta_generic_to_shared(
                    &Ac[(wm * 64 + im * 16 + a_r) * SROW + kk + a_sel]);
                asm volatile(
                    "ldmatrix.sync.aligned.m8n8.x4.shared.b16 {%0,%1,%2,%3}, [%4];"
                    : "=r"(af[im][0]), "=r"(af[im][1]), "=r"(af[im][2]), "=r"(af[im][3])
                    : "r"(addr));
            }
            unsigned bq[2][4];
#pragma unroll
            for (int q = 0; q < 2; q++) {
                unsigned addr = (unsigned)__cvta_generic_to_shared(
                    &Bc[(wn * 32 + q * 16 + b_r) * SROW + kk + b_sel]);
                asm volatile(
                    "ldmatrix.sync.aligned.m8n8.x4.shared.b16 {%0,%1,%2,%3}, [%4];"
                    : "=r"(bq[q][0]), "=r"(bq[q][1]), "=r"(bq[q][2]), "=r"(bq[q][3])
                    : "r"(addr));
            }
#pragma unroll
            for (int im = 0; im < 4; im++) {
#pragma unroll
                for (int in = 0; in < 4; in++) {
                    unsigned b0 = bq[in >> 1][(in & 1) * 2];
                    unsigned b1 = bq[in >> 1][(in & 1) * 2 + 1];
                    asm volatile(
                        "mma.sync.aligned.m16n8k16.row.col.f16.f16.f16.f16 "
                        "{%0,%1}, {%2,%3,%4,%5}, {%6,%7}, {%0,%1};"
                        : "+r"(acc[im][in][0]), "+r"(acc[im][in][1])
                        : "r"(af[im][0]), "r"(af[im][1]), "r"(af[im][2]), "r"(af[im][3]),
                          "r"(b0), "r"(b1));
                }
            }
        }
        __syncthreads();
    }

    // fused affinity epilogue
    const int gr = lane >> 2;
    const int gc = (lane & 3) * 2;
    float numL = 0.0f, denL = 0.0f;
#pragma unroll
    for (int im = 0; im < 4; im++) {
#pragma unroll
        for (int in = 0; in < 4; in++) {
#pragma unroll
            for (int r = 0; r < 4; r++) {
                __half2 h2 = *(__half2*)&acc[im][in][r >> 1];
                float v = (r & 1) ? __high2float(h2) : __low2float(h2);
                if (v > SIM_TH) {
                    int row = wm * 64 + im * 16 + gr + ((r >> 1) << 3);
                    int col = wn * 32 + in * 8 + gc + (r & 1);
                    denL += 1.0f;
                    float d = 0.0f;
#pragma unroll
                    for (int k = 0; k < KK; k++)
                        d += fabsf(Ms[k * 128 + row] - Mt[k * 128 + col]);
                    numL += d;
                }
            }
        }
    }
    numL *= w;
    denL *= w;

#pragma unroll
    for (int off = 16; off > 0; off >>= 1) {
        numL += __shfl_xor_sync(0xFFFFFFFFu, numL, off);
        denL += __shfl_xor_sync(0xFFFFFFFFu, denL, off);
    }
    if (lane == 0) { red[wid] = numL; red[8 + wid] = denL; }
    __syncthreads();
    if (tid == 0) {
        float n = 0.0f, d = 0.0f;
#pragma unroll
        for (int q = 0; q < 8; q++) { n += red[q]; d += red[8 + q]; }
        atomicAdd(&g_num, n);
        atomicAdd(&g_den, d);
        __threadfence();
        unsigned t = atomicAdd(&g_done, 1u);
        if (t == GRID2 - 1) {
            out[0] = g_num / (g_den + EPS_DEN);
        }
    }
}

extern "C" void kernel_launch(void* const* d_in, const int* in_sizes, int n_in,
                              void* d_out, int out_size)
{
    const float* masks   = (const float*)d_in[0];
    const float* feats   = (const float*)d_in[1];
    const int*   indices = (const int*)d_in[2];
    float* out = (float*)d_out;

    cudaFuncSetAttribute(gram_affinity_kernel,
                         cudaFuncAttributeMaxDynamicSharedMemorySize, SMEM_BYTES);

    prep_kernel<<<BB, 512>>>(indices);
    gather_kernel<<<512, 256>>>(masks, feats);
    gram_affinity_kernel<<<GRID2, 256, SMEM_BYTES>>>(out);
}

// round 7
// speedup vs baseline: 1.6433x; 1.6433x over previous
#include <cuda_runtime.h>
#include <cuda_fp16.h>
#include <math.h>
#include <cstdint>

// Problem constants
#define BB   2
#define KK   8
#define CC   256
#define HW   16384
#define SS   2048
#define SIM_TH 0.95f
#define EPS_DEN 1e-6f
#define EPS_NRM 1e-12f

// Gram tiling
#define TM 128
#define TN 128
#define KC 32
#define NT (SS / TM)                  // 16
#define NPAIR ((NT * (NT + 1)) / 2)   // 136
#define GRID2 (BB * NPAIR)            // 272
#define SROW 40                       // padded smem row (f16)

// Scratch (no allocation allowed)
__device__ __align__(16) __half g_fh[BB][SS][CC];
__device__ float g_m[BB][KK][SS];
__device__ int   g_order[BB][SS];     // (hw<<16) | s, bucket-sorted by hw
__device__ float g_num;
__device__ float g_den;
__device__ unsigned g_done;

// cp.async helpers
#define CP_ASYNC16(dst_smem_u32, src_gptr) \
    asm volatile("cp.async.cg.shared.global [%0], [%1], 16;" \
                 :: "r"(dst_smem_u32), "l"(src_gptr))
#define CP_COMMIT() asm volatile("cp.async.commit_group;" ::: "memory")
#define CP_WAIT0()  asm volatile("cp.async.wait_group 0;" ::: "memory")
#define CP_WAIT1()  asm volatile("cp.async.wait_group 1;" ::: "memory")

// ---------------------------------------------------------------------------
// Kernel 0: bucket-sort samples by hw (1024 buckets of 16 positions).
// grid: BB x 1024. Histogram + two-level warp scan + atomic scatter.
// ---------------------------------------------------------------------------
__global__ __launch_bounds__(1024)
void prep_kernel(const int* __restrict__ indices)
{
    __shared__ int hist[1024];
    __shared__ int wsum[32];

    const int b = blockIdx.x;
    const int tid = threadIdx.x;
    const int lane = tid & 31;
    const int wid = tid >> 5;

    if (b == 0 && tid == 0) { g_num = 0.0f; g_den = 0.0f; g_done = 0u; }

    hist[tid] = 0;
    __syncthreads();

    // histogram: 2 samples per thread
    int hw0 = indices[b * SS + tid];
    int hw1 = indices[b * SS + 1024 + tid];
    atomicAdd(&hist[hw0 >> 4], 1);
    atomicAdd(&hist[hw1 >> 4], 1);
    __syncthreads();

    // two-level exclusive scan over 1024
    int v = hist[tid];
    int incl = v;
#pragma unroll
    for (int off = 1; off < 32; off <<= 1) {
        int n = __shfl_up_sync(0xFFFFFFFFu, incl, off);
        if (lane >= off) incl += n;
    }
    if (lane == 31) wsum[wid] = incl;
    __syncthreads();
    if (wid == 0) {
        int wv = wsum[lane];
        int wi = wv;
#pragma unroll
        for (int off = 1; off < 32; off <<= 1) {
            int n = __shfl_up_sync(0xFFFFFFFFu, wi, off);
            if (lane >= off) wi += n;
        }
        wsum[lane] = wi - wv;     // exclusive warp offsets
    }
    __syncthreads();
    hist[tid] = incl - v + wsum[wid];   // exclusive scan result
    __syncthreads();

    // scatter
    int slot0 = atomicAdd(&hist[hw0 >> 4], 1);
    g_order[b][slot0] = (hw0 << 16) | tid;
    int slot1 = atomicAdd(&hist[hw1 >> 4], 1);
    g_order[b][slot1] = (hw1 << 16) | (1024 + tid);
}

// ---------------------------------------------------------------------------
// Kernel 1: gather in hw-sorted order (DRAM row-buffer friendly).
// One warp per sample; lane covers 8 channels. grid 512 x 256.
// ---------------------------------------------------------------------------
__global__ void gather_kernel(const float* __restrict__ masks,
                              const float* __restrict__ feats)
{
    const int tid  = threadIdx.x;
    const int wid  = tid >> 5;
    const int lane = tid & 31;

    // mask gather (sorted within each k)
    if (tid < 64) {
        int e = blockIdx.x * 64 + tid;          // 32768 = B*K*S
        int b = e / (KK * SS);
        int r = e % (KK * SS);
        int k = r / SS;
        int pos = r % SS;
        int ord = g_order[b][pos];
        int hw = ord >> 16;
        int s  = ord & 0xFFFF;
        float x = masks[(b * KK + k) * HW + hw];
        g_m[b][k][s] = 1.0f / (1.0f + expf(-x));
    }

    const int gwarp = blockIdx.x * 8 + wid;     // 0..4095
    const int b   = gwarp >> 11;
    const int pos = gwarp & 2047;
    const int ord = g_order[b][pos];
    const int hw  = ord >> 16;
    const int s   = ord & 0xFFFF;

    float v[8];
    float ss = 0.0f;
#pragma unroll
    for (int u = 0; u < 8; u++) {
        int c = u * 32 + lane;
        float x = feats[((size_t)(b * CC + c)) * HW + hw];
        v[u] = x;
        ss += x * x;
    }
#pragma unroll
    for (int off = 16; off > 0; off >>= 1)
        ss += __shfl_xor_sync(0xFFFFFFFFu, ss, off);

    float inv = 1.0f / fmaxf(sqrtf(ss), EPS_NRM);
#pragma unroll
    for (int u = 0; u < 8; u++) {
        int c = u * 32 + lane;
        g_fh[b][s][c] = __float2half(v[u] * inv);
    }
}

// ---------------------------------------------------------------------------
// Kernel 2: f16 mma.sync Gram (fp16 acc) + fused affinity + final scalar.
// 256 threads, 8 warps (2x4), warp tile 64x32, KC=32 double-buffered,
// ~49 KB smem => 4 CTAs/SM.
// ---------------------------------------------------------------------------
#define STAGE_ELEMS (TM * SROW)
#define SMEM_AB     (2 * 2 * STAGE_ELEMS)
#define SMEM_BYTES  (SMEM_AB * 2 + (2 * KK * 128 + 16) * 4)

__global__ __launch_bounds__(256, 4)
void gram_affinity_kernel(float* __restrict__ out)
{
    extern __shared__ __align__(16) char dyn[];
    __half* As = (__half*)dyn;                   // [2][128][40]
    __half* Bs = As + 2 * STAGE_ELEMS;           // [2][128][40]
    float* Ms  = (float*)(dyn + SMEM_AB * 2);    // [8][128]
    float* Mt  = Ms + KK * 128;                  // [8][128]
    float* red = Mt + KK * 128;                  // [16]

    const int tid = threadIdx.x;
    const int b = blockIdx.x / NPAIR;
    int p = blockIdx.x % NPAIR;

    int j = 0;
    while (((j + 1) * (j + 2)) / 2 <= p) j++;
    int i = p - (j * (j + 1)) / 2;

    const int s0 = i * TM;
    const int t0 = j * TN;
    const float w = (i == j) ? 1.0f : 2.0f;

    const int lane = tid & 31;
    const int wid  = tid >> 5;
    const int wm   = wid & 1;
    const int wn   = wid >> 1;

    const int lrow = tid >> 2;              // rows 0..63 (then +64)
    const int lch  = (tid & 3) * 8;         // f16 col (16B granule)

    const uint32_t as_base = (uint32_t)__cvta_generic_to_shared(As);
    const uint32_t bs_base = (uint32_t)__cvta_generic_to_shared(Bs);

    // stage 0
#pragma unroll
    for (int it = 0; it < 2; it++) {
        int row = lrow + it * 64;
        uint32_t soff = (uint32_t)(row * SROW + lch) * 2;
        CP_ASYNC16(as_base + soff, &g_fh[b][s0 + row][lch]);
        CP_ASYNC16(bs_base + soff, &g_fh[b][t0 + row][lch]);
    }
    CP_COMMIT();

    // m tiles while stage 0 is in flight
#pragma unroll
    for (int it = 0; it < 4; it++) {
        int q = tid + it * 256;
        int k = q >> 7;
        int r = q & 127;
        Ms[k * 128 + r] = g_m[b][k][s0 + r];
        Mt[k * 128 + r] = g_m[b][k][t0 + r];
    }

    uint32_t acc[4][4][2];
#pragma unroll
    for (int im = 0; im < 4; im++)
#pragma unroll
        for (int in = 0; in < 4; in++) { acc[im][in][0] = 0u; acc[im][in][1] = 0u; }

    const int a_r   = lane & 15;
    const int a_sel = (lane >> 4) << 3;
    const int b_r   = (lane & 7) + ((lane >> 4) << 3);
    const int b_sel = ((lane >> 3) & 1) << 3;

#pragma unroll 1
    for (int ck = 0; ck < 8; ck++) {
        if (ck < 7) {
            const int kcn = (ck + 1) * KC;
            const int stn = (ck + 1) & 1;
#pragma unroll
            for (int it = 0; it < 2; it++) {
                int row = lrow + it * 64;
                uint32_t soff = (uint32_t)(stn * STAGE_ELEMS + row * SROW + lch) * 2;
                CP_ASYNC16(as_base + soff, &g_fh[b][s0 + row][kcn + lch]);
                CP_ASYNC16(bs_base + soff, &g_fh[b][t0 + row][kcn + lch]);
            }
            CP_COMMIT();
            CP_WAIT1();
        } else {
            CP_WAIT0();
        }
        __syncthreads();

        const int st = ck & 1;
        __half* Ac = As + st * STAGE_ELEMS;
        __half* Bc = Bs + st * STAGE_ELEMS;

#pragma unroll
        for (int kk = 0; kk < KC; kk += 16) {
            unsigned af[4][4];
#pragma unroll
            for (int im = 0; im < 4; im++) {
                unsigned addr = (unsigned)__cvta_generic_to_shared(
                    &Ac[(wm * 64 + im * 16 + a_r) * SROW + kk + a_sel]);
                asm volatile(
                    "ldmatrix.sync.aligned.m8n8.x4.shared.b16 {%0,%1,%2,%3}, [%4];"
                    : "=r"(af[im][0]), "=r"(af[im][1]), "=r"(af[im][2]), "=r"(af[im][3])
                    : "r"(addr));
            }
            unsigned bq[2][4];
#pragma unroll
            for (int q = 0; q < 2; q++) {
                unsigned addr = (unsigned)__cvta_generic_to_shared(
                    &Bc[(wn * 32 + q * 16 + b_r) * SROW + kk + b_sel]);
                asm volatile(
                    "ldmatrix.sync.aligned.m8n8.x4.shared.b16 {%0,%1,%2,%3}, [%4];"
                    : "=r"(bq[q][0]), "=r"(bq[q][1]), "=r"(bq[q][2]), "=r"(bq[q][3])
                    : "r"(addr));
            }
#pragma unroll
            for (int im = 0; im < 4; im++) {
#pragma unroll
                for (int in = 0; in < 4; in++) {
                    unsigned b0 = bq[in >> 1][(in & 1) * 2];
                    unsigned b1 = bq[in >> 1][(in & 1) * 2 + 1];
                    asm volatile(
                        "mma.sync.aligned.m16n8k16.row.col.f16.f16.f16.f16 "
                        "{%0,%1}, {%2,%3,%4,%5}, {%6,%7}, {%0,%1};"
                        : "+r"(acc[im][in][0]), "+r"(acc[im][in][1])
                        : "r"(af[im][0]), "r"(af[im][1]), "r"(af[im][2]), "r"(af[im][3]),
                          "r"(b0), "r"(b1));
                }
            }
        }
        __syncthreads();
    }

    // fused affinity epilogue
    const int gr = lane >> 2;
    const int gc = (lane & 3) * 2;
    float numL = 0.0f, denL = 0.0f;
#pragma unroll
    for (int im = 0; im < 4; im++) {
#pragma unroll
        for (int in = 0; in < 4; in++) {
#pragma unroll
            for (int r = 0; r < 4; r++) {
                __half2 h2 = *(__half2*)&acc[im][in][r >> 1];
                float v = (r & 1) ? __high2float(h2) : __low2float(h2);
                if (v > SIM_TH) {
                    int row = wm * 64 + im * 16 + gr + ((r >> 1) << 3);
                    int col = wn * 32 + in * 8 + gc + (r & 1);
                    denL += 1.0f;
                    float d = 0.0f;
#pragma unroll
                    for (int k = 0; k < KK; k++)
                        d += fabsf(Ms[k * 128 + row] - Mt[k * 128 + col]);
                    numL += d;
                }
            }
        }
    }
    numL *= w;
    denL *= w;

#pragma unroll
    for (int off = 16; off > 0; off >>= 1) {
        numL += __shfl_xor_sync(0xFFFFFFFFu, numL, off);
        denL += __shfl_xor_sync(0xFFFFFFFFu, denL, off);
    }
    if (lane == 0) { red[wid] = numL; red[8 + wid] = denL; }
    __syncthreads();
    if (tid == 0) {
        float n = 0.0f, d = 0.0f;
#pragma unroll
        for (int q = 0; q < 8; q++) { n += red[q]; d += red[8 + q]; }
        atomicAdd(&g_num, n);
        atomicAdd(&g_den, d);
        __threadfence();
        unsigned t = atomicAdd(&g_done, 1u);
        if (t == GRID2 - 1) {
            out[0] = g_num / (g_den + EPS_DEN);
        }
    }
}

extern "C" void kernel_launch(void* const* d_in, const int* in_sizes, int n_in,
                              void* d_out, int out_size)
{
    const float* masks   = (const float*)d_in[0];
    const float* feats   = (const float*)d_in[1];
    const int*   indices = (const int*)d_in[2];
    float* out = (float*)d_out;

    cudaFuncSetAttribute(gram_affinity_kernel,
                         cudaFuncAttributeMaxDynamicSharedMemorySize, SMEM_BYTES);

    prep_kernel<<<BB, 1024>>>(indices);
    gather_kernel<<<512, 256>>>(masks, feats);
    gram_affinity_kernel<<<GRID2, 256, SMEM_BYTES>>>(out);
}